// round 7
// baseline (speedup 1.0000x reference)
#include <cuda_runtime.h>

// Problem constants
#define Bn  16
#define Cn  32
#define Nn  128
#define Tn  12
#define COn 64
#define NT  (Nn * Tn)          // 1536 floats per (b,i,j) row of A
#define NT4 (NT / 4)           // 384 float4
#define NSLICE (Bn * Cn)       // 512 (b,i) slices

// prop config: 128 persistent CTAs (1/SM via big smem), 768 threads =
// 4 groups x 192; each group streams 32 of the 128 j-rows.
#define PROP_CTAS    128
#define PROP_THREADS 768
#define NGRP 4
#define GSZ  192
#define JPG  (Nn / NGRP)       // 32
#define JC   7                 // j-rows per group cached in smem for pass 2
#define JNC  (JPG - JC)        // 25 uncached
#define ACACHE_BYTES (NGRP * JC * NT4 * 16)   // 168 KB dynamic smem

// Scratch: h = concat([x1, x2], channel axis) -> [B][2C][N*T] = 6.3 MB
__device__ float g_h[(size_t)Bn * 2 * Cn * NT];

__device__ __forceinline__ void fma4(float4& acc, const float4 a, const float4 v) {
    acc.x = fmaf(a.x, v.x, acc.x);
    acc.y = fmaf(a.y, v.y, acc.y);
    acc.z = fmaf(a.z, v.z, acc.z);
    acc.w = fmaf(a.w, v.w, acc.w);
}
__device__ __forceinline__ float4 add4(const float4 a, const float4 b) {
    return make_float4(a.x + b.x, a.y + b.y, a.z + b.z, a.w + b.w);
}

// packed fp32x2 helpers (Blackwell)
#define FMA2(d, a, b) asm("fma.rn.f32x2 %0, %1, %2, %0;" : "+l"(d) : "l"(a), "l"(b))
__device__ __forceinline__ unsigned long long dup2(float w) {
    unsigned long long r;
    asm("mov.b64 %0, {%1, %1};" : "=l"(r) : "f"(w));
    return r;
}

// ---------------------------------------------------------------------------
// Kernel 1: fused order-1 + order-2 propagation (R3 structure), with the
// last JC j-rows of each group's A panel cached in smem during pass 1 so
// pass 2 re-reads 7/32 of the slice from smem instead of L2.
// Chip-wide phase lockstep keeps the concurrent L2 footprint at
// 128 x 786KB = 100MB <= 126MB (proven in R3).
// ---------------------------------------------------------------------------
extern __shared__ float4 acache[];   // [NGRP][JC][NT4]

__global__ __launch_bounds__(PROP_THREADS, 1)
void prop_kernel(const float* __restrict__ x, const float* __restrict__ A) {
    __shared__ float4 part[NGRP][NT4];   // 24 KB partial sums
    __shared__ float4 xs[NT4];           // x slice,  [j*3 + lq]
    __shared__ float4 x1s[NT4];          // x1 slice, same layout

    const int t  = threadIdx.x;
    const int g  = t / GSZ;
    const int ti = t - g * GSZ;          // 0..191
    const int lq = ti % 3;
    const int j0 = g * JPG;
    float4* cache = acache + (size_t)g * JC * NT4;

    for (int bc = blockIdx.x; bc < NSLICE; bc += PROP_CTAS) {
        const float4* __restrict__ xp = (const float4*)(x + (size_t)bc * NT);
        const float4* __restrict__ Ap = (const float4*)(A + (size_t)bc * Nn * NT);

        if (t < NT4) xs[t] = xp[t];
        __syncthreads();   // also the end-of-previous-iteration barrier

        // ---- Pass 1: x1[k,l] = sum_j x[j,l] * A[j,k,l]  (HBM stream)
        float4 acc0 = make_float4(0.f, 0.f, 0.f, 0.f);
        float4 acc1 = make_float4(0.f, 0.f, 0.f, 0.f);
        {
            const float4* __restrict__ ap = Ap + (size_t)j0 * NT4;
#pragma unroll 5
            for (int jj = 0; jj < JNC; ++jj) {
                float4 a0 = ap[jj * NT4 + ti];
                float4 a1 = ap[jj * NT4 + ti + GSZ];
                float4 xv = xs[(j0 + jj) * 3 + lq];
                fma4(acc0, a0, xv);
                fma4(acc1, a1, xv);
            }
            // last JC rows: also stash in smem for pass 2
#pragma unroll
            for (int jj = JNC; jj < JPG; ++jj) {
                float4 a0 = ap[jj * NT4 + ti];
                float4 a1 = ap[jj * NT4 + ti + GSZ];
                float4 xv = xs[(j0 + jj) * 3 + lq];
                cache[(jj - JNC) * NT4 + ti]       = a0;
                cache[(jj - JNC) * NT4 + ti + GSZ] = a1;
                fma4(acc0, a0, xv);
                fma4(acc1, a1, xv);
            }
        }
        part[g][ti]       = acc0;
        part[g][ti + GSZ] = acc1;
        __syncthreads();

        // ---- Reduce 1: x1 = sum of 4 partials
        float4 r1;
        if (t < NT4) {
            r1 = add4(add4(part[0][t], part[1][t]), add4(part[2][t], part[3][t]));
            x1s[t] = r1;
        }
        __syncthreads();

        // ---- Pass 2: uncached rows from L2, cached rows from smem
        acc0 = make_float4(0.f, 0.f, 0.f, 0.f);
        acc1 = make_float4(0.f, 0.f, 0.f, 0.f);
        {
            const float4* __restrict__ ap = Ap + (size_t)j0 * NT4;
#pragma unroll 5
            for (int jj = 0; jj < JNC; ++jj) {
                float4 a0 = ap[jj * NT4 + ti];
                float4 a1 = ap[jj * NT4 + ti + GSZ];
                float4 xv = x1s[(j0 + jj) * 3 + lq];
                fma4(acc0, a0, xv);
                fma4(acc1, a1, xv);
            }
#pragma unroll
            for (int jj = JNC; jj < JPG; ++jj) {
                float4 a0 = cache[(jj - JNC) * NT4 + ti];
                float4 a1 = cache[(jj - JNC) * NT4 + ti + GSZ];
                float4 xv = x1s[(j0 + jj) * 3 + lq];
                fma4(acc0, a0, xv);
                fma4(acc1, a1, xv);
            }
        }
        part[g][ti]       = acc0;
        part[g][ti + GSZ] = acc1;
        __syncthreads();

        // ---- Reduce 2 + write h[b,i,:] = x1, h[b,C+i,:] = x2
        if (t < NT4) {
            float4 r2 = add4(add4(part[0][t], part[1][t]), add4(part[2][t], part[3][t]));
            const int b = bc / Cn;
            const int i = bc % Cn;
            ((float4*)(g_h + ((size_t)b * 2 * Cn + i) * NT))[t]      = r1;
            ((float4*)(g_h + ((size_t)b * 2 * Cn + Cn + i) * NT))[t] = r2;
        }
    }
}

// ---------------------------------------------------------------------------
// Kernel 2: 1x1 conv channel mix, smem GEMM with packed f32x2 FMAs.
// Block: 256 threads, tile = 64 outs x 64 cols. Thread (oq=t/16, colq=t%16)
// computes 4 outs x 4 cols held as 8 packed f32x2 accumulators.
// W is pre-duplicated in smem as (w,w) u64 pairs, layout [c][o] so the
// 4 w's per c are two LDS128. Per c: 3 LDS + 8 FFMA2 (was 5 LDS + 16 FFMA).
// ---------------------------------------------------------------------------
#define MIX_COLS 64
#define MIX_NCB  (NT / MIX_COLS)   // 24

typedef unsigned long long u64;

__global__ __launch_bounds__(256) void mix_kernel(const float* __restrict__ W,
                                                  const float* __restrict__ bias,
                                                  float* __restrict__ out) {
    __shared__ float4 hs[(2 * Cn) * (MIX_COLS / 4)];   // [c][16] float4, 16 KB
    __shared__ u64    W2t[2 * Cn * COn];               // [c][o] dup pairs, 32 KB
    __shared__ float  bs[COn];

    const int t    = threadIdx.x;
    const int b    = blockIdx.x / MIX_NCB;
    const int col0 = (blockIdx.x % MIX_NCB) * MIX_COLS;
    const int colq = t & 15;
    const int oq   = t >> 4;

    // Build W2t: read W [o][c] as float4 (coalesced), scatter dup pairs to [c][o]
    {
        const float4* W4 = (const float4*)W;
#pragma unroll
        for (int s = 0; s < 4; ++s) {
            int fidx = t + 256 * s;          // 0..1023 float4s of W
            int o    = fidx >> 4;
            int c4   = fidx & 15;
            float4 w = W4[fidx];
            W2t[(4 * c4 + 0) * COn + o] = dup2(w.x);
            W2t[(4 * c4 + 1) * COn + o] = dup2(w.y);
            W2t[(4 * c4 + 2) * COn + o] = dup2(w.z);
            W2t[(4 * c4 + 3) * COn + o] = dup2(w.w);
        }
        if (t < COn) bs[t] = bias[t];
    }
    // Load h tile: 64 channels x 16 float4 (coalesced per channel row)
    {
        const float* hb = g_h + (size_t)b * 2 * Cn * NT + col0;
#pragma unroll
        for (int s = 0; s < 4; ++s) {
            int idx = t + 256 * s;
            int c   = idx >> 4;
            int v   = idx & 15;
            hs[idx] = ((const float4*)(hb + (size_t)c * NT))[v];
        }
    }
    __syncthreads();

    // 8 packed accumulators: acc[o'][half], o' = 0..3 -> out row 4*oq+o'
    u64 a00 = dup2(bs[4 * oq + 0]), a01 = a00;
    u64 a10 = dup2(bs[4 * oq + 1]), a11 = a10;
    u64 a20 = dup2(bs[4 * oq + 2]), a21 = a20;
    u64 a30 = dup2(bs[4 * oq + 3]), a31 = a30;

    const ulonglong2* hs2 = (const ulonglong2*)hs;   // hs2[c*16 + colq]
#pragma unroll 8
    for (int c = 0; c < 2 * Cn; ++c) {
        ulonglong2 hv = hs2[c * 16 + colq];          // cols 0-1, 2-3 packed
        const ulonglong2* wp = (const ulonglong2*)(W2t + c * COn + 4 * oq);
        ulonglong2 wA = wp[0];                        // o0, o1 dup pairs
        ulonglong2 wB = wp[1];                        // o2, o3 dup pairs
        FMA2(a00, wA.x, hv.x); FMA2(a01, wA.x, hv.y);
        FMA2(a10, wA.y, hv.x); FMA2(a11, wA.y, hv.y);
        FMA2(a20, wB.x, hv.x); FMA2(a21, wB.x, hv.y);
        FMA2(a30, wB.y, hv.x); FMA2(a31, wB.y, hv.y);
    }

    float* ob = out + (size_t)b * COn * NT + col0;
    ulonglong2 r;
    r.x = a00; r.y = a01;
    ((ulonglong2*)(ob + (size_t)(4 * oq + 0) * NT))[colq] = r;
    r.x = a10; r.y = a11;
    ((ulonglong2*)(ob + (size_t)(4 * oq + 1) * NT))[colq] = r;
    r.x = a20; r.y = a21;
    ((ulonglong2*)(ob + (size_t)(4 * oq + 2) * NT))[colq] = r;
    r.x = a30; r.y = a31;
    ((ulonglong2*)(ob + (size_t)(4 * oq + 3) * NT))[colq] = r;
}

// ---------------------------------------------------------------------------
extern "C" void kernel_launch(void* const* d_in, const int* in_sizes, int n_in,
                              void* d_out, int out_size) {
    const float* x    = (const float*)d_in[0];   // [B,C,N,T]
    const float* A    = (const float*)d_in[1];   // [B,C,N,N,T]
    const float* W    = (const float*)d_in[2];   // [C_OUT, 2C]
    const float* bias = (const float*)d_in[3];   // [C_OUT]
    float* out = (float*)d_out;                  // [B,C_OUT,N,T]

    cudaFuncSetAttribute(prop_kernel, cudaFuncAttributeMaxDynamicSharedMemorySize,
                         ACACHE_BYTES);

    prop_kernel<<<PROP_CTAS, PROP_THREADS, ACACHE_BYTES>>>(x, A);
    mix_kernel<<<Bn * MIX_NCB, 256>>>(W, bias, out);
}

// round 8
// speedup vs baseline: 1.2781x; 1.2781x over previous
#include <cuda_runtime.h>
#include <cstdint>

// Problem constants
#define Bn  16
#define Cn  32
#define Nn  128
#define Tn  12
#define COn 64
#define NT  (Nn * Tn)          // 1536 floats per (b,i,j) row of A
#define NT4 (NT / 4)           // 384
#define NSLICE (Bn * Cn)       // 512
#define NPAIR  64              // CTA pairs; pair q handles slices q, q+64, ...
#define SPP    (NSLICE / NPAIR)  // 8 slices per pair

// k-split halves
#define HALF   768             // floats per half j-row
#define HALF4  192             // float4 per half j-row
// pipeline
#define TJ     8               // j-rows per tile
#define TILE_BYTES (TJ * HALF * 4)   // 24576
#define NTILE  (Nn / TJ)       // 16 tiles per pass
#define NSTAGE 8
#define CONS   192             // consumer threads (6 warps)
#define THREADS 224            // + 1 producer warp
#define SMEM_TOTAL (NSTAGE * TILE_BYTES + 2 * NT4 * 16 + 128)   // 209024

// Scratch: h = concat([x1, x2], channel axis) -> [B][2C][N*T] = 6.3 MB
__device__ float g_h[(size_t)Bn * 2 * Cn * NT];
// monotonic pair-exchange flags (never reset; graph-replay safe)
__device__ unsigned long long g_flag[NPAIR][2];

__device__ __forceinline__ void fma4(float4& acc, const float4 a, const float4 v) {
    acc.x = fmaf(a.x, v.x, acc.x);
    acc.y = fmaf(a.y, v.y, acc.y);
    acc.z = fmaf(a.z, v.z, acc.z);
    acc.w = fmaf(a.w, v.w, acc.w);
}

__device__ __forceinline__ uint32_t smem_u32(const void* p) {
    uint32_t a;
    asm("{ .reg .u64 t; cvta.to.shared.u64 t, %1; cvt.u32.u64 %0, t; }" : "=r"(a) : "l"(p));
    return a;
}

#define MBAR_INIT(addr, cnt) \
    asm volatile("mbarrier.init.shared.b64 [%0], %1;" :: "r"(addr), "r"(cnt) : "memory")
#define MBAR_EXPECT_TX(addr, bytes) \
    asm volatile("mbarrier.arrive.expect_tx.shared.b64 _, [%0], %1;" :: "r"(addr), "r"(bytes) : "memory")
#define MBAR_ARRIVE(addr) \
    asm volatile("mbarrier.arrive.shared.b64 _, [%0];" :: "r"(addr) : "memory")

#define MBAR_WAIT_PARITY(mbar, ph) do {                                        \
    uint32_t _m = (mbar), _p = (uint32_t)(ph), _done;                          \
    asm volatile("{\n\t.reg .pred p;\n\t"                                      \
        "mbarrier.try_wait.parity.acquire.cta.shared::cta.b64 p, [%1], %2;\n\t"\
        "selp.b32 %0, 1, 0, p;\n\t}"                                           \
        : "=r"(_done) : "r"(_m), "r"(_p) : "memory");                          \
    if (!_done) {                                                              \
        asm volatile("{\n\t.reg .pred P1;\n\t"                                 \
            "WL_%=:\n\t"                                                       \
            "mbarrier.try_wait.parity.acquire.cta.shared::cta.b64 P1, [%0], %1, 0x989680;\n\t" \
            "@P1 bra.uni WD_%=;\n\t"                                           \
            "bra.uni WL_%=;\n\t"                                               \
            "WD_%=:\n\t}"                                                      \
            :: "r"(_m), "r"(_p) : "memory");                                   \
    }                                                                          \
} while (0)

__device__ __forceinline__ void bulk_g2s(uint32_t dst, const void* src,
                                         uint32_t bytes, uint32_t mbar) {
    asm volatile(
        "cp.async.bulk.shared::cta.global.mbarrier::complete_tx::bytes [%0], [%1], %2, [%3];"
        :: "r"(dst), "l"(src), "r"(bytes), "r"(mbar) : "memory");
}

__device__ __forceinline__ unsigned long long ld_vol(const unsigned long long* p) {
    unsigned long long v;
    asm volatile("ld.volatile.global.u64 %0, [%1];" : "=l"(v) : "l"(p));
    return v;
}

// ---------------------------------------------------------------------------
// Kernel 1: fused order-1/order-2 propagation as a bulk-copy pipeline.
// 128 CTAs = 64 pairs; rank r owns the k-half (bytes [r*3KB, r*3KB+3KB) of
// every 6KB j-row). Producer thread streams the tile sequence
// [P1(s) x16, P2(s) x16, P1(s+64) x16, ...] into an 8-stage smem ring via
// cp.async.bulk (bypasses L1tex FIFO -> DRAM fills of s+1 overlap L2
// re-reads of s). 192 consumer threads each own one output float4 across
// the full j loop (no partial reduction needed). x1 halves exchanged
// between pair CTAs through g_h + monotonic flags.
// ---------------------------------------------------------------------------
__global__ __launch_bounds__(THREADS, 1)
void prop_kernel(const float* __restrict__ x, const float* __restrict__ A) {
    extern __shared__ char dsm[];
    float4*   stages = (float4*)dsm;                               // 8 x 24KB
    float4*   xs     = (float4*)(dsm + NSTAGE * TILE_BYTES);       // 384
    float4*   x1buf  = xs + NT4;                                   // 384
    uint64_t* mbars  = (uint64_t*)(x1buf + NT4);                   // full[8], empty[8]

    const int tid = threadIdx.x;
    const int r   = blockIdx.x & 1;         // k-half rank
    const int q   = blockIdx.x >> 1;        // pair index
    const int pr  = 1 - r;

    const uint32_t mb0 = smem_u32(mbars);
    // full[i] at mb0 + 16*i, empty[i] at mb0 + 16*i + 8
    if (tid == 0) {
#pragma unroll
        for (int i = 0; i < NSTAGE; ++i) {
            MBAR_INIT(mb0 + 16 * i, 1);        // full: producer expect_tx
            MBAR_INIT(mb0 + 16 * i + 8, 6);    // empty: 6 consumer warps
        }
    }
    __syncthreads();

    if (tid >= CONS) {
        // ---------------- Producer (single thread) ----------------
        if (tid == CONS) {
            const uint32_t st0 = smem_u32(stages);
            int pstage = 0, pphase = 1;
            for (int it = 0; it < SPP; ++it) {
                const int s = q + it * NPAIR;
                const float* sl = A + (size_t)s * Nn * NT + r * HALF;
#pragma unroll 1
                for (int pass = 0; pass < 2; ++pass) {
#pragma unroll 1
                    for (int tile = 0; tile < NTILE; ++tile) {
                        MBAR_WAIT_PARITY(mb0 + 16 * pstage + 8, pphase);
                        MBAR_EXPECT_TX(mb0 + 16 * pstage, TILE_BYTES);
                        uint32_t dst = st0 + pstage * TILE_BYTES;
                        const float* src = sl + (size_t)(tile * TJ) * NT;
#pragma unroll
                        for (int jj = 0; jj < TJ; ++jj)
                            bulk_g2s(dst + jj * (HALF * 4), src + (size_t)jj * NT,
                                     HALF * 4, mb0 + 16 * pstage);
                        if (++pstage == NSTAGE) { pstage = 0; pphase ^= 1; }
                    }
                }
            }
        }
        return;
    }

    // ---------------- Consumers (192 threads, 6 warps) ----------------
    const int t  = tid;            // 0..191: owns output float4 (k = 64r + t/3, l0 = 4*(t%3))
    const int lq = t % 3;
    const unsigned long long base_peer = ld_vol(&g_flag[q][pr]);

    int cstage = 0, cphase = 0;
    const float4* x4 = (const float4*)x;

    for (int it = 0; it < SPP; ++it) {
        const int s = q + it * NPAIR;
        const int b = s / Cn;
        const int i = s % Cn;

        // load x slice (full 1536 floats)
        xs[t]        = x4[(size_t)s * NT4 + t];
        xs[t + CONS] = x4[(size_t)s * NT4 + t + CONS];
        asm volatile("bar.sync 1, %0;" :: "r"(CONS) : "memory");

        // ---- Pass 1: x1_half[t] = sum_j x[j,l] * A[j,k,l]
        float4 acc = make_float4(0.f, 0.f, 0.f, 0.f);
        for (int tile = 0; tile < NTILE; ++tile) {
            MBAR_WAIT_PARITY(mb0 + 16 * cstage, cphase);
            const float4* st = stages + (size_t)cstage * (TJ * HALF4);
            const float4* xb = xs + tile * TJ * 3 + lq;
#pragma unroll
            for (int jj = 0; jj < TJ; ++jj)
                fma4(acc, st[jj * HALF4 + t], xb[jj * 3]);
            __syncwarp();
            if ((tid & 31) == 0) MBAR_ARRIVE(mb0 + 16 * cstage + 8);
            if (++cstage == NSTAGE) { cstage = 0; cphase ^= 1; }
        }

        // ---- publish x1 half, exchange with peer
        float4* hrow1 = (float4*)(g_h + ((size_t)b * 2 * Cn + i) * NT);
        hrow1[CONS * r + t] = acc;
        x1buf[CONS * r + t] = acc;
        __threadfence();
        atomicAdd(&g_flag[q][r], 1ULL);

        if (t == 0) {
            const unsigned long long tgt = base_peer + (unsigned long long)CONS * (it + 1);
            while (ld_vol(&g_flag[q][pr]) < tgt) { }
            __threadfence();
        }
        asm volatile("bar.sync 1, %0;" :: "r"(CONS) : "memory");
        x1buf[CONS * pr + t] = hrow1[CONS * pr + t];
        asm volatile("bar.sync 1, %0;" :: "r"(CONS) : "memory");

        // ---- Pass 2: x2_half[t] = sum_j x1[j,l] * A[j,k,l]
        acc = make_float4(0.f, 0.f, 0.f, 0.f);
        for (int tile = 0; tile < NTILE; ++tile) {
            MBAR_WAIT_PARITY(mb0 + 16 * cstage, cphase);
            const float4* st = stages + (size_t)cstage * (TJ * HALF4);
            const float4* xb = x1buf + tile * TJ * 3 + lq;
#pragma unroll
            for (int jj = 0; jj < TJ; ++jj)
                fma4(acc, st[jj * HALF4 + t], xb[jj * 3]);
            __syncwarp();
            if ((tid & 31) == 0) MBAR_ARRIVE(mb0 + 16 * cstage + 8);
            if (++cstage == NSTAGE) { cstage = 0; cphase ^= 1; }
        }

        ((float4*)(g_h + ((size_t)b * 2 * Cn + Cn + i) * NT))[CONS * r + t] = acc;
    }
}

// ---------------------------------------------------------------------------
// Kernel 2: 1x1 conv channel mix, smem-tiled GEMM (exact R3 version, 10.6us).
// ---------------------------------------------------------------------------
#define MIX_COLS 64
#define MIX_NCB  (NT / MIX_COLS)   // 24

__global__ __launch_bounds__(256) void mix_kernel(const float* __restrict__ W,
                                                  const float* __restrict__ bias,
                                                  float* __restrict__ out) {
    __shared__ float4 hs[(2 * Cn) * (MIX_COLS / 4)];   // 16 KB
    __shared__ float  Ws[COn * 2 * Cn];                // 16 KB
    __shared__ float  bs[COn];

    const int t    = threadIdx.x;
    const int b    = blockIdx.x / MIX_NCB;
    const int col0 = (blockIdx.x % MIX_NCB) * MIX_COLS;
    const int colq = t & 15;
    const int oq   = t >> 4;

    {
        float4*       Wd = (float4*)Ws;
        const float4* W4 = (const float4*)W;
#pragma unroll
        for (int s = 0; s < 4; ++s) Wd[t + 256 * s] = W4[t + 256 * s];
        if (t < COn) bs[t] = bias[t];
    }
    {
        const float* hb = g_h + (size_t)b * 2 * Cn * NT + col0;
#pragma unroll
        for (int s = 0; s < 4; ++s) {
            int idx = t + 256 * s;
            int c   = idx >> 4;
            int v   = idx & 15;
            hs[idx] = ((const float4*)(hb + (size_t)c * NT))[v];
        }
    }
    __syncthreads();

    float4 acc0 = make_float4(bs[4 * oq + 0], bs[4 * oq + 0], bs[4 * oq + 0], bs[4 * oq + 0]);
    float4 acc1 = make_float4(bs[4 * oq + 1], bs[4 * oq + 1], bs[4 * oq + 1], bs[4 * oq + 1]);
    float4 acc2 = make_float4(bs[4 * oq + 2], bs[4 * oq + 2], bs[4 * oq + 2], bs[4 * oq + 2]);
    float4 acc3 = make_float4(bs[4 * oq + 3], bs[4 * oq + 3], bs[4 * oq + 3], bs[4 * oq + 3]);

#pragma unroll 8
    for (int c = 0; c < 2 * Cn; ++c) {
        float4 hv = hs[c * 16 + colq];
        float  w0 = Ws[(4 * oq + 0) * 2 * Cn + c];
        float  w1 = Ws[(4 * oq + 1) * 2 * Cn + c];
        float  w2 = Ws[(4 * oq + 2) * 2 * Cn + c];
        float  w3 = Ws[(4 * oq + 3) * 2 * Cn + c];
        acc0.x = fmaf(w0, hv.x, acc0.x); acc0.y = fmaf(w0, hv.y, acc0.y);
        acc0.z = fmaf(w0, hv.z, acc0.z); acc0.w = fmaf(w0, hv.w, acc0.w);
        acc1.x = fmaf(w1, hv.x, acc1.x); acc1.y = fmaf(w1, hv.y, acc1.y);
        acc1.z = fmaf(w1, hv.z, acc1.z); acc1.w = fmaf(w1, hv.w, acc1.w);
        acc2.x = fmaf(w2, hv.x, acc2.x); acc2.y = fmaf(w2, hv.y, acc2.y);
        acc2.z = fmaf(w2, hv.z, acc2.z); acc2.w = fmaf(w2, hv.w, acc2.w);
        acc3.x = fmaf(w3, hv.x, acc3.x); acc3.y = fmaf(w3, hv.y, acc3.y);
        acc3.z = fmaf(w3, hv.z, acc3.z); acc3.w = fmaf(w3, hv.w, acc3.w);
    }

    float* ob = out + (size_t)b * COn * NT + col0;
    ((float4*)(ob + (size_t)(4 * oq + 0) * NT))[colq] = acc0;
    ((float4*)(ob + (size_t)(4 * oq + 1) * NT))[colq] = acc1;
    ((float4*)(ob + (size_t)(4 * oq + 2) * NT))[colq] = acc2;
    ((float4*)(ob + (size_t)(4 * oq + 3) * NT))[colq] = acc3;
}

// ---------------------------------------------------------------------------
extern "C" void kernel_launch(void* const* d_in, const int* in_sizes, int n_in,
                              void* d_out, int out_size) {
    const float* x    = (const float*)d_in[0];   // [B,C,N,T]
    const float* A    = (const float*)d_in[1];   // [B,C,N,N,T]
    const float* W    = (const float*)d_in[2];   // [C_OUT, 2C]
    const float* bias = (const float*)d_in[3];   // [C_OUT]
    float* out = (float*)d_out;                  // [B,C_OUT,N,T]

    cudaFuncSetAttribute(prop_kernel, cudaFuncAttributeMaxDynamicSharedMemorySize,
                         SMEM_TOTAL);

    prop_kernel<<<2 * NPAIR, THREADS, SMEM_TOTAL>>>(x, A);
    mix_kernel<<<Bn * MIX_NCB, 256>>>(W, bias, out);
}